// round 14
// baseline (speedup 1.0000x reference)
#include <cuda_runtime.h>
#include <cuda_bf16.h>
#include <stdint.h>

#define NA 4096
#define NB 4096
#define D  256
#define H  4
#define DK 64

#define QM 64             // query rows per CTA (4 warps x m16)
#define BN 64             // kv cols per iteration
#define NIT (NB / BN)     // 64

#define LOG2E    1.4426950408889634f
#define TENLOG2E 14.426950408889634f

#define PTILE 64
#define PSTR  68

// smem tile geometry: 64 rows x 64 bf16, row stride 72 bf16 (144 B)
#define ARRB   9216           // 64 * 144 bytes per array
#define BUFB   36864          // 4 arrays (Khi,Klo,VThi,VTlo)
#define SME_TOT (2 * BUFB)    // double buffered (73728 B)

// ---- device globals ------------------------------------------------------
__device__ __nv_bfloat16 g_Qhi[(size_t)NA * D], g_Qlo[(size_t)NA * D];
__device__ __nv_bfloat16 g_Khi[(size_t)NB * D], g_Klo[(size_t)NB * D];
__device__ __nv_bfloat16 g_VThi[(size_t)D * NB], g_VTlo[(size_t)D * NB];
__device__ float g_CTX[(size_t)H * NA * DK];

// ---- helpers -------------------------------------------------------------
__device__ __forceinline__ uint32_t smem_u32(const void* p) {
    uint32_t a;
    asm("{ .reg .u64 t; cvta.to.shared.u64 t, %1; cvt.u32.u64 %0, t; }"
        : "=r"(a) : "l"(p));
    return a;
}
__device__ __forceinline__ float ex2f(float x) {
    float y; asm("ex2.approx.f32 %0, %1;" : "=f"(y) : "f"(x)); return y;
}
__device__ __forceinline__ void cp16(uint32_t dst, const void* src) {
    asm volatile("cp.async.cg.shared.global [%0], [%1], 16;" :: "r"(dst), "l"(src));
}
#define CP_COMMIT() asm volatile("cp.async.commit_group;" ::: "memory")
#define CP_WAIT0()  asm volatile("cp.async.wait_group 0;" ::: "memory")

// ldmatrix x4: 4 8x8 b16 tiles. Lane l supplies row address of tile l>>3.
__device__ __forceinline__ void ldsm4(uint32_t d[4], uint32_t a) {
    asm volatile("ldmatrix.sync.aligned.m8n8.x4.shared.b16 {%0,%1,%2,%3}, [%4];"
        : "=r"(d[0]), "=r"(d[1]), "=r"(d[2]), "=r"(d[3]) : "r"(a));
}

// mma.sync m16n8k16 bf16 -> f32 (baseline sm_80+ PTX)
__device__ __forceinline__ void hmma(float c[4],
    uint32_t a0, uint32_t a1, uint32_t a2, uint32_t a3,
    uint32_t b0, uint32_t b1)
{
    asm volatile(
        "mma.sync.aligned.m16n8k16.row.col.f32.bf16.bf16.f32 "
        "{%0,%1,%2,%3}, {%4,%5,%6,%7}, {%8,%9}, {%0,%1,%2,%3};"
        : "+f"(c[0]), "+f"(c[1]), "+f"(c[2]), "+f"(c[3])
        : "r"(a0), "r"(a1), "r"(a2), "r"(a3), "r"(b0), "r"(b1));
}

// pack {lo=a, hi=b} as bf16x2
__device__ __forceinline__ uint32_t cvt2(float a, float b) {
    uint32_t r;
    asm("cvt.rn.bf16x2.f32 %0, %1, %2;" : "=r"(r) : "f"(b), "f"(a));
    return r;
}

// ---------------------------------------------------------------------------
// Projection: dst = src @ W^T, epilogue emits bf16 hi/lo splits.
// mat 0: Q -> g_Qhi/lo [NA][D]; 1: K -> g_Khi/lo; 2: V -> transposed g_VThi/lo [D][NB]
// ---------------------------------------------------------------------------
__global__ __launch_bounds__(256) void proj_kernel(
    const float* __restrict__ a_z, const float* __restrict__ bv_z,
    const float* __restrict__ Wq, const float* __restrict__ Wk,
    const float* __restrict__ Wv)
{
    __shared__ float a_s[16][PSTR];
    __shared__ float w_s[16][PSTR];
    const int mat = blockIdx.z;
    const float* __restrict__ src = (mat == 0) ? a_z : bv_z;
    const float* __restrict__ W   = (mat == 0) ? Wq : ((mat == 1) ? Wk : Wv);

    const int m0 = blockIdx.x * PTILE;
    const int n0 = blockIdx.y * PTILE;
    const int tid = threadIdx.x;
    const int tx = tid & 15, ty = tid >> 4;
    const int lr = tid >> 2;
    const int lc = (tid & 3) * 4;

    float acc[4][4] = {};

    for (int k0 = 0; k0 < D; k0 += 16) {
        float4 av = *(const float4*)(src + (size_t)(m0 + lr) * D + k0 + lc);
        float4 wv = *(const float4*)(W   + (size_t)(n0 + lr) * D + k0 + lc);
        a_s[lc + 0][lr] = av.x; a_s[lc + 1][lr] = av.y;
        a_s[lc + 2][lr] = av.z; a_s[lc + 3][lr] = av.w;
        w_s[lc + 0][lr] = wv.x; w_s[lc + 1][lr] = wv.y;
        w_s[lc + 2][lr] = wv.z; w_s[lc + 3][lr] = wv.w;
        __syncthreads();
        #pragma unroll
        for (int kk = 0; kk < 16; kk++) {
            float4 aa = *(const float4*)&a_s[kk][ty * 4];
            float4 bb = *(const float4*)&w_s[kk][tx * 4];
            float ar4[4] = {aa.x, aa.y, aa.z, aa.w};
            float br4[4] = {bb.x, bb.y, bb.z, bb.w};
            #pragma unroll
            for (int i = 0; i < 4; i++)
                #pragma unroll
                for (int j = 0; j < 4; j++)
                    acc[i][j] = fmaf(ar4[i], br4[j], acc[i][j]);
        }
        __syncthreads();
    }

    if (mat == 2) {
        #pragma unroll
        for (int i = 0; i < 4; i++) {
            int m = m0 + ty * 4 + i;
            #pragma unroll
            for (int j = 0; j < 4; j++) {
                int n = n0 + tx * 4 + j;
                float x = acc[i][j];
                __nv_bfloat16 h = __float2bfloat16_rn(x);
                __nv_bfloat16 l = __float2bfloat16_rn(x - __bfloat162float(h));
                g_VThi[(size_t)n * NB + m] = h;
                g_VTlo[(size_t)n * NB + m] = l;
            }
        }
    } else {
        __nv_bfloat16* dh = mat ? g_Khi : g_Qhi;
        __nv_bfloat16* dl = mat ? g_Klo : g_Qlo;
        #pragma unroll
        for (int i = 0; i < 4; i++) {
            int m = m0 + ty * 4 + i;
            size_t base = (size_t)m * D + n0 + tx * 4;
            uint32_t hp[2], lp[2];
            #pragma unroll
            for (int jj = 0; jj < 2; jj++) {
                float x0 = acc[i][2 * jj], x1 = acc[i][2 * jj + 1];
                uint32_t h = cvt2(x0, x1);
                float h0f = __uint_as_float(h << 16);
                float h1f = __uint_as_float(h & 0xffff0000u);
                hp[jj] = h;
                lp[jj] = cvt2(x0 - h0f, x1 - h1f);
            }
            *(uint2*)(dh + base) = make_uint2(hp[0], hp[1]);
            *(uint2*)(dl + base) = make_uint2(lp[0], lp[1]);
        }
    }
}

// ---------------------------------------------------------------------------
// HMMA flash attention. CTA = 64 q rows x 1 head, 128 threads (4 warps x m16),
// __launch_bounds__(128,2) -> 2 CTAs/SM so independent CTAs overlap the
// epilogue/ldsm phase of one with the HMMA phase of the other.
// Split-bf16: QK^T and PV each use 3 mma.sync per chunk (hi*hi + hi*lo + lo*hi).
// Fixed softmax max = 10 -> no online rescaling; O accumulates in registers.
// mask/weight folded inline (wsel = m ? w : -1e30; clip makes masked == -10).
// ---------------------------------------------------------------------------
__device__ __forceinline__ void cpload(uint32_t smb, int buf, int b0, int hh, int tid)
{
    const uint32_t dstb = smb + buf * BUFB;
    #pragma unroll
    for (int u = 0; u < 16; u++) {
        int f = tid + u * 128;            // 0..2047
        int arr = f >> 9;                 // 0..3 (compile-time per u)
        int r = (f >> 3) & 63;
        int j = f & 7;
        const __nv_bfloat16* s;
        if (arr == 0)      s = g_Khi  + (size_t)(b0 + r) * D + hh * DK + j * 8;
        else if (arr == 1) s = g_Klo  + (size_t)(b0 + r) * D + hh * DK + j * 8;
        else if (arr == 2) s = g_VThi + (size_t)(hh * DK + r) * NB + b0 + j * 8;
        else               s = g_VTlo + (size_t)(hh * DK + r) * NB + b0 + j * 8;
        cp16(dstb + arr * ARRB + r * 144 + j * 16, s);
    }
}

__global__ __launch_bounds__(128, 2) void attn_kernel(
    const int* __restrict__ mask, const float* __restrict__ weight)
{
    extern __shared__ uint8_t sm[];
    const uint32_t smb = smem_u32(sm);
    const int tid = threadIdx.x;
    const int w = tid >> 5;           // 0..3
    const int lane = tid & 31;
    const int g = lane >> 2;          // 0..7
    const int i4 = lane & 3;          // 0..3
    const int a0 = blockIdx.x * QM;
    const int hh = blockIdx.y;
    const int qr0 = a0 + w * 16 + g;
    const int qr1 = qr0 + 8;

    // per-thread ldmatrix row offset: tile m = lane>>3, row r = lane&7
    const int lm = lane >> 3;
    const uint32_t rb144 = (uint32_t)(((lm >> 1) * 8 + (lane & 7)) * 144 + (lm & 1) * 16);

    // Q A-fragments (held in registers for all 64 iterations)
    uint32_t qa[2][4][4];
    #pragma unroll
    for (int sp = 0; sp < 2; sp++) {
        const __nv_bfloat16* Qs = sp ? g_Qlo : g_Qhi;
        const __nv_bfloat16* q0 = Qs + (size_t)qr0 * D + hh * DK;
        const __nv_bfloat16* q1 = Qs + (size_t)qr1 * D + hh * DK;
        #pragma unroll
        for (int kc = 0; kc < 4; kc++) {
            qa[sp][kc][0] = *(const uint32_t*)(q0 + kc * 16 + 2 * i4);
            qa[sp][kc][1] = *(const uint32_t*)(q1 + kc * 16 + 2 * i4);
            qa[sp][kc][2] = *(const uint32_t*)(q0 + kc * 16 + 8 + 2 * i4);
            qa[sp][kc][3] = *(const uint32_t*)(q1 + kc * 16 + 8 + 2 * i4);
        }
    }

    cpload(smb, 0, 0, hh, tid);
    CP_COMMIT();

    float oc[8][4] = {};
    float lsum0 = 0.0f, lsum1 = 0.0f;

    const int*   mk0base = mask   + (size_t)qr0 * NB + 2 * i4;
    const int*   mk1base = mask   + (size_t)qr1 * NB + 2 * i4;
    const float* wt0base = weight + (size_t)qr0 * NB + 2 * i4;
    const float* wt1base = weight + (size_t)qr1 * NB + 2 * i4;

    for (int nt = 0; nt < NIT; nt++) {
        // prefetch mask+weight for this tile FIRST; latency overlaps MMA phase.
        // select immediately so only the folded wsel values stay live.
        float2 wv0[8], wv1[8];
        {
            const int*   m0p = mk0base + nt * BN;
            const int*   m1p = mk1base + nt * BN;
            const float* w0p = wt0base + nt * BN;
            const float* w1p = wt1base + nt * BN;
            #pragma unroll
            for (int n = 0; n < 8; n++) {
                int2   m0 = *(const int2*)(m0p + n * 8);
                int2   m1 = *(const int2*)(m1p + n * 8);
                float2 t0 = *(const float2*)(w0p + n * 8);
                float2 t1 = *(const float2*)(w1p + n * 8);
                wv0[n] = make_float2(m0.x ? t0.x : -1e30f, m0.y ? t0.y : -1e30f);
                wv1[n] = make_float2(m1.x ? t1.x : -1e30f, m1.y ? t1.y : -1e30f);
            }
        }

        CP_WAIT0();
        __syncthreads();
        if (nt + 1 < NIT) { cpload(smb, (nt + 1) & 1, (nt + 1) * BN, hh, tid); CP_COMMIT(); }

        const uint32_t B  = smb + (nt & 1) * BUFB;
        const uint32_t KH = B + rb144, KL = B + ARRB + rb144;
        const uint32_t VH = B + 2 * ARRB + rb144, VL = B + 3 * ARRB + rb144;

        // ---- S = Q K^T (3 split MMAs per chunk; B-frags via ldmatrix.x4) ----
        float sc[8][4];
        #pragma unroll
        for (int n = 0; n < 8; n++)
            #pragma unroll
            for (int c = 0; c < 4; c++) sc[n][c] = 0.0f;

        #pragma unroll
        for (int kc = 0; kc < 4; kc++) {
            #pragma unroll
            for (int p = 0; p < 4; p++) {
                uint32_t off = (uint32_t)(p * 2304 + kc * 32);
                uint32_t kh[4], kl[4];
                ldsm4(kh, KH + off);
                ldsm4(kl, KL + off);
                int n0 = 2 * p, n1 = 2 * p + 1;
                hmma(sc[n0], qa[0][kc][0], qa[0][kc][1], qa[0][kc][2], qa[0][kc][3], kh[0], kh[1]);
                hmma(sc[n0], qa[0][kc][0], qa[0][kc][1], qa[0][kc][2], qa[0][kc][3], kl[0], kl[1]);
                hmma(sc[n0], qa[1][kc][0], qa[1][kc][1], qa[1][kc][2], qa[1][kc][3], kh[0], kh[1]);
                hmma(sc[n1], qa[0][kc][0], qa[0][kc][1], qa[0][kc][2], qa[0][kc][3], kh[2], kh[3]);
                hmma(sc[n1], qa[0][kc][0], qa[0][kc][1], qa[0][kc][2], qa[0][kc][3], kl[2], kl[3]);
                hmma(sc[n1], qa[1][kc][0], qa[1][kc][1], qa[1][kc][2], qa[1][kc][3], kh[2], kh[3]);
            }
        }

        // ---- epilogue: s/8 + wsel, clip, p = 2^(s*log2e - 10*log2e), split P ----
        uint32_t ph01[8], ph23[8], pl01[8], pl23[8];
        #pragma unroll
        for (int n = 0; n < 8; n++) {
            float s0 = fminf(fmaxf(fmaf(sc[n][0], 0.125f, wv0[n].x), -10.0f), 10.0f);
            float s1 = fminf(fmaxf(fmaf(sc[n][1], 0.125f, wv0[n].y), -10.0f), 10.0f);
            float s2 = fminf(fmaxf(fmaf(sc[n][2], 0.125f, wv1[n].x), -10.0f), 10.0f);
            float s3 = fminf(fmaxf(fmaf(sc[n][3], 0.125f, wv1[n].y), -10.0f), 10.0f);
            float p0 = ex2f(fmaf(s0, LOG2E, -TENLOG2E));
            float p1 = ex2f(fmaf(s1, LOG2E, -TENLOG2E));
            float p2 = ex2f(fmaf(s2, LOG2E, -TENLOG2E));
            float p3 = ex2f(fmaf(s3, LOG2E, -TENLOG2E));
            lsum0 += p0 + p1;
            lsum1 += p2 + p3;
            uint32_t h01 = cvt2(p0, p1);
            uint32_t h23 = cvt2(p2, p3);
            ph01[n] = h01; ph23[n] = h23;
            pl01[n] = cvt2(p0 - __uint_as_float(h01 << 16),
                           p1 - __uint_as_float(h01 & 0xffff0000u));
            pl23[n] = cvt2(p2 - __uint_as_float(h23 << 16),
                           p3 - __uint_as_float(h23 & 0xffff0000u));
        }

        // ---- O += P V (A-frags from acc layout; B-frags via ldmatrix.x4) ----
        #pragma unroll
        for (int kc = 0; kc < 4; kc++) {
            uint32_t ah0 = ph01[2 * kc], ah1 = ph23[2 * kc];
            uint32_t ah2 = ph01[2 * kc + 1], ah3 = ph23[2 * kc + 1];
            uint32_t al0 = pl01[2 * kc], al1 = pl23[2 * kc];
            uint32_t al2 = pl01[2 * kc + 1], al3 = pl23[2 * kc + 1];
            #pragma unroll
            for (int p = 0; p < 4; p++) {
                uint32_t off = (uint32_t)(p * 2304 + kc * 32);
                uint32_t vh[4], vl[4];
                ldsm4(vh, VH + off);
                ldsm4(vl, VL + off);
                int d0i = 2 * p, d1i = 2 * p + 1;
                hmma(oc[d0i], ah0, ah1, ah2, ah3, vh[0], vh[1]);
                hmma(oc[d0i], al0, al1, al2, al3, vh[0], vh[1]);
                hmma(oc[d0i], ah0, ah1, ah2, ah3, vl[0], vl[1]);
                hmma(oc[d1i], ah0, ah1, ah2, ah3, vh[2], vh[3]);
                hmma(oc[d1i], al0, al1, al2, al3, vh[2], vh[3]);
                hmma(oc[d1i], ah0, ah1, ah2, ah3, vl[2], vl[3]);
            }
        }
    }

    // ---- finalize: reduce lsum across quad, normalize, store ----
    lsum0 += __shfl_xor_sync(0xffffffffu, lsum0, 1);
    lsum0 += __shfl_xor_sync(0xffffffffu, lsum0, 2);
    lsum1 += __shfl_xor_sync(0xffffffffu, lsum1, 1);
    lsum1 += __shfl_xor_sync(0xffffffffu, lsum1, 2);
    const float inv0 = 1.0f / lsum0;
    const float inv1 = 1.0f / lsum1;

    float* d0 = g_CTX + ((size_t)hh * NA + qr0) * DK;
    float* d1 = g_CTX + ((size_t)hh * NA + qr1) * DK;
    #pragma unroll
    for (int nd = 0; nd < 8; nd++) {
        *(float2*)(d0 + nd * 8 + 2 * i4) = make_float2(oc[nd][0] * inv0, oc[nd][1] * inv0);
        *(float2*)(d1 + nd * 8 + 2 * i4) = make_float2(oc[nd][2] * inv1, oc[nd][3] * inv1);
    }
}

// ---------------------------------------------------------------------------
// head mean + influence (softmax rows sum to 1 -> influence == 1.0 exactly)
// ---------------------------------------------------------------------------
__global__ void combine_kernel(float* __restrict__ out)
{
    int idx = blockIdx.x * blockDim.x + threadIdx.x;
    if (idx < NA * DK) {
        float s = g_CTX[idx] + g_CTX[NA * DK + idx] +
                  g_CTX[2 * NA * DK + idx] + g_CTX[3 * NA * DK + idx];
        out[idx] = s * 0.25f;
    }
    if (idx < NA) out[NA * DK + idx] = 1.0f;
}

// ---------------------------------------------------------------------------
extern "C" void kernel_launch(void* const* d_in, const int* in_sizes, int n_in,
                              void* d_out, int out_size)
{
    const float* a_z    = (const float*)d_in[0];
    const float* bv_z   = (const float*)d_in[1];
    const int*   mask   = (const int*)d_in[2];   // jnp bool -> int32 per harness
    const float* weight = (const float*)d_in[3];
    const float* Wq     = (const float*)d_in[4];
    const float* Wk     = (const float*)d_in[5];
    const float* Wv     = (const float*)d_in[6];
    float* out = (float*)d_out;

    cudaFuncSetAttribute(attn_kernel,
                         cudaFuncAttributeMaxDynamicSharedMemorySize, SME_TOT);

    proj_kernel<<<dim3(NA / PTILE, D / PTILE, 3), 256>>>(a_z, bv_z, Wq, Wk, Wv);
    attn_kernel<<<dim3(NA / QM, H), 128, SME_TOT>>>(mask, weight);
    combine_kernel<<<(NA * DK + 255) / 256, 256>>>(out);
}

// round 16
// speedup vs baseline: 1.0739x; 1.0739x over previous
#include <cuda_runtime.h>
#include <cuda_bf16.h>
#include <stdint.h>

#define NA 4096
#define NB 4096
#define D  256
#define H  4
#define DK 64

#define QM 128            // query rows per CTA (8 warps x m16)
#define BN 64             // kv cols per iteration
#define NIT (NB / BN)     // 64

#define LOG2E    1.4426950408889634f
#define TENLOG2E 14.426950408889634f

#define PTILE 64
#define PSTR  68

// smem tile geometry: 64 rows x 64 bf16, row stride 72 bf16 (144 B)
#define ARRB   9216           // 64 * 144 bytes per array
#define BUFB   36864          // 4 arrays (Khi,Klo,VThi,VTlo)
#define SME_TOT (3 * BUFB)    // TRIPLE buffered (110592 B) for sw pipeline

// ---- device globals ------------------------------------------------------
__device__ __nv_bfloat16 g_Qhi[(size_t)NA * D], g_Qlo[(size_t)NA * D];
__device__ __nv_bfloat16 g_Khi[(size_t)NB * D], g_Klo[(size_t)NB * D];
__device__ __nv_bfloat16 g_VThi[(size_t)D * NB], g_VTlo[(size_t)D * NB];
__device__ float g_WB[(size_t)NA * NB];
__device__ float g_CTX[(size_t)H * NA * DK];

// ---- helpers -------------------------------------------------------------
__device__ __forceinline__ uint32_t smem_u32(const void* p) {
    uint32_t a;
    asm("{ .reg .u64 t; cvta.to.shared.u64 t, %1; cvt.u32.u64 %0, t; }"
        : "=r"(a) : "l"(p));
    return a;
}
__device__ __forceinline__ float ex2f(float x) {
    float y; asm("ex2.approx.f32 %0, %1;" : "=f"(y) : "f"(x)); return y;
}
__device__ __forceinline__ void cp16(uint32_t dst, const void* src) {
    asm volatile("cp.async.cg.shared.global [%0], [%1], 16;" :: "r"(dst), "l"(src));
}
#define CP_COMMIT() asm volatile("cp.async.commit_group;" ::: "memory")
#define CP_WAIT0()  asm volatile("cp.async.wait_group 0;" ::: "memory")

// ldmatrix x4: 4 8x8 b16 tiles. Lane l supplies row address of tile l>>3.
__device__ __forceinline__ void ldsm4(uint32_t d[4], uint32_t a) {
    asm volatile("ldmatrix.sync.aligned.m8n8.x4.shared.b16 {%0,%1,%2,%3}, [%4];"
        : "=r"(d[0]), "=r"(d[1]), "=r"(d[2]), "=r"(d[3]) : "r"(a));
}

// mma.sync m16n8k16 bf16 -> f32 (baseline sm_80+ PTX)
__device__ __forceinline__ void hmma(float c[4],
    uint32_t a0, uint32_t a1, uint32_t a2, uint32_t a3,
    uint32_t b0, uint32_t b1)
{
    asm volatile(
        "mma.sync.aligned.m16n8k16.row.col.f32.bf16.bf16.f32 "
        "{%0,%1,%2,%3}, {%4,%5,%6,%7}, {%8,%9}, {%0,%1,%2,%3};"
        : "+f"(c[0]), "+f"(c[1]), "+f"(c[2]), "+f"(c[3])
        : "r"(a0), "r"(a1), "r"(a2), "r"(a3), "r"(b0), "r"(b1));
}

// pack {lo=a, hi=b} as bf16x2
__device__ __forceinline__ uint32_t cvt2(float a, float b) {
    uint32_t r;
    asm("cvt.rn.bf16x2.f32 %0, %1, %2;" : "=r"(r) : "f"(b), "f"(a));
    return r;
}

// ---------------------------------------------------------------------------
// Projection: dst = src @ W^T, epilogue emits bf16 hi/lo splits.
// ---------------------------------------------------------------------------
__global__ __launch_bounds__(256) void proj_kernel(
    const float* __restrict__ a_z, const float* __restrict__ bv_z,
    const float* __restrict__ Wq, const float* __restrict__ Wk,
    const float* __restrict__ Wv)
{
    __shared__ float a_s[16][PSTR];
    __shared__ float w_s[16][PSTR];
    const int mat = blockIdx.z;
    const float* __restrict__ src = (mat == 0) ? a_z : bv_z;
    const float* __restrict__ W   = (mat == 0) ? Wq : ((mat == 1) ? Wk : Wv);

    const int m0 = blockIdx.x * PTILE;
    const int n0 = blockIdx.y * PTILE;
    const int tid = threadIdx.x;
    const int tx = tid & 15, ty = tid >> 4;
    const int lr = tid >> 2;
    const int lc = (tid & 3) * 4;

    float acc[4][4] = {};

    for (int k0 = 0; k0 < D; k0 += 16) {
        float4 av = *(const float4*)(src + (size_t)(m0 + lr) * D + k0 + lc);
        float4 wv = *(const float4*)(W   + (size_t)(n0 + lr) * D + k0 + lc);
        a_s[lc + 0][lr] = av.x; a_s[lc + 1][lr] = av.y;
        a_s[lc + 2][lr] = av.z; a_s[lc + 3][lr] = av.w;
        w_s[lc + 0][lr] = wv.x; w_s[lc + 1][lr] = wv.y;
        w_s[lc + 2][lr] = wv.z; w_s[lc + 3][lr] = wv.w;
        __syncthreads();
        #pragma unroll
        for (int kk = 0; kk < 16; kk++) {
            float4 aa = *(const float4*)&a_s[kk][ty * 4];
            float4 bb = *(const float4*)&w_s[kk][tx * 4];
            float ar4[4] = {aa.x, aa.y, aa.z, aa.w};
            float br4[4] = {bb.x, bb.y, bb.z, bb.w};
            #pragma unroll
            for (int i = 0; i < 4; i++)
                #pragma unroll
                for (int j = 0; j < 4; j++)
                    acc[i][j] = fmaf(ar4[i], br4[j], acc[i][j]);
        }
        __syncthreads();
    }

    if (mat == 2) {
        #pragma unroll
        for (int i = 0; i < 4; i++) {
            int m = m0 + ty * 4 + i;
            #pragma unroll
            for (int j = 0; j < 4; j++) {
                int n = n0 + tx * 4 + j;
                float x = acc[i][j];
                __nv_bfloat16 h = __float2bfloat16_rn(x);
                __nv_bfloat16 l = __float2bfloat16_rn(x - __bfloat162float(h));
                g_VThi[(size_t)n * NB + m] = h;
                g_VTlo[(size_t)n * NB + m] = l;
            }
        }
    } else {
        __nv_bfloat16* dh = mat ? g_Khi : g_Qhi;
        __nv_bfloat16* dl = mat ? g_Klo : g_Qlo;
        #pragma unroll
        for (int i = 0; i < 4; i++) {
            int m = m0 + ty * 4 + i;
            size_t base = (size_t)m * D + n0 + tx * 4;
            uint32_t hp[2], lp[2];
            #pragma unroll
            for (int jj = 0; jj < 2; jj++) {
                float x0 = acc[i][2 * jj], x1 = acc[i][2 * jj + 1];
                uint32_t h = cvt2(x0, x1);
                float h0f = __uint_as_float(h << 16);
                float h1f = __uint_as_float(h & 0xffff0000u);
                hp[jj] = h;
                lp[jj] = cvt2(x0 - h0f, x1 - h1f);
            }
            *(uint2*)(dh + base) = make_uint2(hp[0], hp[1]);
            *(uint2*)(dl + base) = make_uint2(lp[0], lp[1]);
        }
    }
}

// ---------------------------------------------------------------------------
// wb = mask ? weight : -1e30 (clamps to exactly -10 after clip in attention)
// ---------------------------------------------------------------------------
__global__ void wb_kernel(const int* __restrict__ mask, const float* __restrict__ w)
{
    size_t i = ((size_t)blockIdx.x * blockDim.x + threadIdx.x) * 4;
    int4 m = *(const int4*)(mask + i);
    float4 wv = *(const float4*)(w + i);
    float4 o;
    o.x = m.x ? wv.x : -1e30f;
    o.y = m.y ? wv.y : -1e30f;
    o.z = m.z ? wv.z : -1e30f;
    o.w = m.w ? wv.w : -1e30f;
    *(float4*)(g_WB + i) = o;
}

// ---------------------------------------------------------------------------
// HMMA flash attention, software-pipelined: epilogue(nt) interleaved with
// QK(nt+1) so FMA/MUFU and LDSM/HMMA stalls fill each other. Triple-buffered
// K/V smem. CTA = 128 q rows x 1 head, 256 threads. Fixed softmax max = 10.
// ---------------------------------------------------------------------------
__device__ __forceinline__ void cpload(uint32_t smb, int buf, int b0, int hh, int tid)
{
    const uint32_t dstb = smb + buf * BUFB;
    #pragma unroll
    for (int u = 0; u < 8; u++) {
        int f = tid + u * 256;            // 0..2047
        int arr = f >> 9;                 // 0..3
        int r = (f >> 3) & 63;
        int j = f & 7;
        const __nv_bfloat16* s;
        if (arr == 0)      s = g_Khi  + (size_t)(b0 + r) * D + hh * DK + j * 8;
        else if (arr == 1) s = g_Klo  + (size_t)(b0 + r) * D + hh * DK + j * 8;
        else if (arr == 2) s = g_VThi + (size_t)(hh * DK + r) * NB + b0 + j * 8;
        else               s = g_VTlo + (size_t)(hh * DK + r) * NB + b0 + j * 8;
        cp16(dstb + arr * ARRB + r * 144 + j * 16, s);
    }
}

// one (kc,p) QK sub-step: 2 ldsm4 + 6 hmma into dst[2p], dst[2p+1]
__device__ __forceinline__ void qk_step(float dst[8][4],
    const uint32_t qa[2][4][4], uint32_t KH, uint32_t KL, int s)
{
    const int kc = s >> 2, p = s & 3;
    const uint32_t off = (uint32_t)(p * 2304 + kc * 32);
    uint32_t kh[4], kl[4];
    ldsm4(kh, KH + off);
    ldsm4(kl, KL + off);
    hmma(dst[2*p],   qa[0][kc][0], qa[0][kc][1], qa[0][kc][2], qa[0][kc][3], kh[0], kh[1]);
    hmma(dst[2*p],   qa[0][kc][0], qa[0][kc][1], qa[0][kc][2], qa[0][kc][3], kl[0], kl[1]);
    hmma(dst[2*p],   qa[1][kc][0], qa[1][kc][1], qa[1][kc][2], qa[1][kc][3], kh[0], kh[1]);
    hmma(dst[2*p+1], qa[0][kc][0], qa[0][kc][1], qa[0][kc][2], qa[0][kc][3], kh[2], kh[3]);
    hmma(dst[2*p+1], qa[0][kc][0], qa[0][kc][1], qa[0][kc][2], qa[0][kc][3], kl[2], kl[3]);
    hmma(dst[2*p+1], qa[1][kc][0], qa[1][kc][1], qa[1][kc][2], qa[1][kc][3], kh[2], kh[3]);
}

__global__ __launch_bounds__(256, 1) void attn_kernel()
{
    extern __shared__ uint8_t sm[];
    const uint32_t smb = smem_u32(sm);
    const int tid = threadIdx.x;
    const int w = tid >> 5;
    const int lane = tid & 31;
    const int i4 = lane & 3;
    const int g = lane >> 2;
    const int a0 = blockIdx.x * QM;
    const int hh = blockIdx.y;
    const int qr0 = a0 + w * 16 + g;
    const int qr1 = qr0 + 8;

    const int lm = lane >> 3;
    const uint32_t rb144 = (uint32_t)(((lm >> 1) * 8 + (lane & 7)) * 144 + (lm & 1) * 16);

    // Q A-fragments (registers, all 64 iterations)
    uint32_t qa[2][4][4];
    #pragma unroll
    for (int sp = 0; sp < 2; sp++) {
        const __nv_bfloat16* Qs = sp ? g_Qlo : g_Qhi;
        const __nv_bfloat16* q0 = Qs + (size_t)qr0 * D + hh * DK;
        const __nv_bfloat16* q1 = Qs + (size_t)qr1 * D + hh * DK;
        #pragma unroll
        for (int kc = 0; kc < 4; kc++) {
            qa[sp][kc][0] = *(const uint32_t*)(q0 + kc * 16 + 2 * i4);
            qa[sp][kc][1] = *(const uint32_t*)(q1 + kc * 16 + 2 * i4);
            qa[sp][kc][2] = *(const uint32_t*)(q0 + kc * 16 + 8 + 2 * i4);
            qa[sp][kc][3] = *(const uint32_t*)(q1 + kc * 16 + 8 + 2 * i4);
        }
    }

    // prologue: tile0 loaded+waited, tile1 in flight, QK(0) computed
    cpload(smb, 0, 0, hh, tid);
    CP_COMMIT();
    CP_WAIT0();
    __syncthreads();
    cpload(smb, 1, BN, hh, tid);
    CP_COMMIT();

    float sc[8][4];
    #pragma unroll
    for (int n = 0; n < 8; n++)
        #pragma unroll
        for (int c = 0; c < 4; c++) sc[n][c] = 0.0f;
    {
        const uint32_t KH = smb + rb144, KL = smb + ARRB + rb144;
        #pragma unroll
        for (int s = 0; s < 16; s++) qk_step(sc, qa, KH, KL, s);
    }

    float oc[8][4] = {};
    float lsum0 = 0.0f, lsum1 = 0.0f;

    const float* w0base = g_WB + (size_t)qr0 * NB + 2 * i4;
    const float* w1base = g_WB + (size_t)qr1 * NB + 2 * i4;

    for (int nt = 0; nt < NIT - 1; nt++) {
        // wb prefetch for tile nt (overlaps wait below)
        float2 wv0[8], wv1[8];
        {
            const float* w0p = w0base + nt * BN;
            const float* w1p = w1base + nt * BN;
            #pragma unroll
            for (int n = 0; n < 8; n++) {
                wv0[n] = *(const float2*)(w0p + n * 8);
                wv1[n] = *(const float2*)(w1p + n * 8);
            }
        }

        // tile nt+1 resident after this; all warps past PV(nt-1)
        CP_WAIT0();
        __syncthreads();
        // prefetch tile nt+2 into buffer (nt+2)%3 (tile nt-1's reads are done)
        if (nt + 2 < NIT) {
            int b3 = (nt + 2) % 3;
            cpload(smb, b3, (nt + 2) * BN, hh, tid);
            CP_COMMIT();
        }

        const uint32_t Bc = smb + (uint32_t)(nt % 3) * BUFB;        // current tile
        const uint32_t Bn = smb + (uint32_t)((nt + 1) % 3) * BUFB;  // next tile
        const uint32_t KH2 = Bn + rb144, KL2 = Bn + ARRB + rb144;
        const uint32_t VH = Bc + 2 * ARRB + rb144, VL = Bc + 3 * ARRB + rb144;

        // ---- interleaved: QK(nt+1) -> sc2  ⊗  epilogue(nt): sc -> P ----
        float sc2[8][4];
        #pragma unroll
        for (int n = 0; n < 8; n++)
            #pragma unroll
            for (int c = 0; c < 4; c++) sc2[n][c] = 0.0f;

        uint32_t ph01[8], ph23[8], pl01[8], pl23[8];
        #pragma unroll
        for (int j = 0; j < 8; j++) {
            qk_step(sc2, qa, KH2, KL2, 2 * j);
            qk_step(sc2, qa, KH2, KL2, 2 * j + 1);
            // epilogue element j (independent of the qk_steps above)
            float s0 = fminf(fmaxf(fmaf(sc[j][0], 0.125f, wv0[j].x), -10.0f), 10.0f);
            float s1 = fminf(fmaxf(fmaf(sc[j][1], 0.125f, wv0[j].y), -10.0f), 10.0f);
            float s2 = fminf(fmaxf(fmaf(sc[j][2], 0.125f, wv1[j].x), -10.0f), 10.0f);
            float s3 = fminf(fmaxf(fmaf(sc[j][3], 0.125f, wv1[j].y), -10.0f), 10.0f);
            float p0 = ex2f(fmaf(s0, LOG2E, -TENLOG2E));
            float p1 = ex2f(fmaf(s1, LOG2E, -TENLOG2E));
            float p2 = ex2f(fmaf(s2, LOG2E, -TENLOG2E));
            float p3 = ex2f(fmaf(s3, LOG2E, -TENLOG2E));
            lsum0 += p0 + p1;
            lsum1 += p2 + p3;
            uint32_t h01 = cvt2(p0, p1);
            uint32_t h23 = cvt2(p2, p3);
            ph01[j] = h01; ph23[j] = h23;
            pl01[j] = cvt2(p0 - __uint_as_float(h01 << 16),
                           p1 - __uint_as_float(h01 & 0xffff0000u));
            pl23[j] = cvt2(p2 - __uint_as_float(h23 << 16),
                           p3 - __uint_as_float(h23 & 0xffff0000u));
        }

        // ---- O += P(nt) V(nt) ----
        #pragma unroll
        for (int kc = 0; kc < 4; kc++) {
            uint32_t ah0 = ph01[2 * kc], ah1 = ph23[2 * kc];
            uint32_t ah2 = ph01[2 * kc + 1], ah3 = ph23[2 * kc + 1];
            uint32_t al0 = pl01[2 * kc], al1 = pl23[2 * kc];
            uint32_t al2 = pl01[2 * kc + 1], al3 = pl23[2 * kc + 1];
            #pragma unroll
            for (int p = 0; p < 4; p++) {
                uint32_t off = (uint32_t)(p * 2304 + kc * 32);
                uint32_t vh[4], vl[4];
                ldsm4(vh, VH + off);
                ldsm4(vl, VL + off);
                int d0i = 2 * p, d1i = 2 * p + 1;
                hmma(oc[d0i], ah0, ah1, ah2, ah3, vh[0], vh[1]);
                hmma(oc[d0i], al0, al1, al2, al3, vh[0], vh[1]);
                hmma(oc[d0i], ah0, ah1, ah2, ah3, vl[0], vl[1]);
                hmma(oc[d1i], ah0, ah1, ah2, ah3, vh[2], vh[3]);
                hmma(oc[d1i], al0, al1, al2, al3, vh[2], vh[3]);
                hmma(oc[d1i], ah0, ah1, ah2, ah3, vl[2], vl[3]);
            }
        }

        // rotate S
        #pragma unroll
        for (int n = 0; n < 8; n++)
            #pragma unroll
            for (int c = 0; c < 4; c++) sc[n][c] = sc2[n][c];
    }

    // ---- tail: tile NIT-1 (sc already holds its scores) ----
    {
        const int nt = NIT - 1;
        float2 wv0[8], wv1[8];
        {
            const float* w0p = w0base + nt * BN;
            const float* w1p = w1base + nt * BN;
            #pragma unroll
            for (int n = 0; n < 8; n++) {
                wv0[n] = *(const float2*)(w0p + n * 8);
                wv1[n] = *(const float2*)(w1p + n * 8);
            }
        }
        const uint32_t Bc = smb + (uint32_t)(nt % 3) * BUFB;
        const uint32_t VH = Bc + 2 * ARRB + rb144, VL = Bc + 3 * ARRB + rb144;

        uint32_t ph01[8], ph23[8], pl01[8], pl23[8];
        #pragma unroll
        for (int j = 0; j < 8; j++) {
            float s0 = fminf(fmaxf(fmaf(sc[j][0], 0.125f, wv0[j].x), -10.0f), 10.0f);
            float s1 = fminf(fmaxf(fmaf(sc[j][1], 0.125f, wv0[j].y), -10.0f), 10.0f);
            float s2 = fminf(fmaxf(fmaf(sc[j][2], 0.125f, wv1[j].x), -10.0f), 10.0f);
            float s3 = fminf(fmaxf(fmaf(sc[j][3], 0.125f, wv1[j].y), -10.0f), 10.0f);
            float p0 = ex2f(fmaf(s0, LOG2E, -TENLOG2E));
            float p1 = ex2f(fmaf(s1, LOG2E, -TENLOG2E));
            float p2 = ex2f(fmaf(s2, LOG2E, -TENLOG2E));
            float p3 = ex2f(fmaf(s3, LOG2E, -TENLOG2E));
            lsum0 += p0 + p1;
            lsum1 += p2 + p3;
            uint32_t h01 = cvt2(p0, p1);
            uint32_t h23 = cvt2(p2, p3);
            ph01[j] = h01; ph23[j] = h23;
            pl01[j] = cvt2(p0 - __uint_as_float(h01 << 16),
                           p1 - __uint_as_float(h01 & 0xffff0000u));
            pl23[j] = cvt2(p2 - __uint_as_float(h23 << 16),
                           p3 - __uint_as_float(h23 & 0xffff0000u));
        }
        #pragma unroll
        for (int kc = 0; kc < 4; kc++) {
            uint32_t ah0 = ph01[2 * kc], ah1 = ph23[2 * kc];
            uint32_t ah2 = ph01[2 * kc + 1], ah3 = ph23[2 * kc + 1];
            uint32_t al0 = pl01[2 * kc], al1 = pl23[2 * kc];
            uint32_t al2 = pl01[2 * kc + 1], al3 = pl23[2 * kc + 1];
            #pragma unroll
            for (int p = 0; p < 4; p++) {
                uint32_t off = (uint32_t)(p * 2304 + kc * 32);
                uint32_t vh[4], vl[4];
                ldsm4(vh, VH + off);
                ldsm4(vl, VL + off);
                int d0i = 2 * p, d1i = 2 * p + 1;
                hmma(oc[d0i], ah0, ah1, ah2, ah3, vh[0], vh[1]);
                hmma(oc[d0i], al0, al1, al2, al3, vh[0], vh[1]);
                hmma(oc[d0i], ah0, ah1, ah2, ah3, vl[0], vl[1]);
                hmma(oc[d1i], ah0, ah1, ah2, ah3, vh[2], vh[3]);
                hmma(oc[d1i], al0, al1, al2, al3, vh[2], vh[3]);
                hmma(oc[d1i], ah0, ah1, ah2, ah3, vl[2], vl[3]);
            }
        }
    }

    // ---- finalize ----
    lsum0 += __shfl_xor_sync(0xffffffffu, lsum0, 1);
    lsum0 += __shfl_xor_sync(0xffffffffu, lsum0, 2);
    lsum1 += __shfl_xor_sync(0xffffffffu, lsum1, 1);
    lsum1 += __shfl_xor_sync(0xffffffffu, lsum1, 2);
    const float inv0 = 1.0f / lsum0;
    const float inv1 = 1.0f / lsum1;

    float* d0 = g_CTX + ((size_t)hh * NA + qr0) * DK;
    float* d1 = g_CTX + ((size_t)hh * NA + qr1) * DK;
    #pragma unroll
    for (int nd = 0; nd < 8; nd++) {
        *(float2*)(d0 + nd * 8 + 2 * i4) = make_float2(oc[nd][0] * inv0, oc[nd][1] * inv0);
        *(float2*)(d1 + nd * 8 + 2 * i4) = make_float2(oc[nd][2] * inv1, oc[nd][3] * inv1);
    }
}

// ---------------------------------------------------------------------------
// head mean + influence (softmax rows sum to 1 -> influence == 1.0 exactly)
// ---------------------------------------------------------------------------
__global__ void combine_kernel(float* __restrict__ out)
{
    int idx = blockIdx.x * blockDim.x + threadIdx.x;
    if (idx < NA * DK) {
        float s = g_CTX[idx] + g_CTX[NA * DK + idx] +
                  g_CTX[2 * NA * DK + idx] + g_CTX[3 * NA * DK + idx];
        out[idx] = s * 0.25f;
    }
    if (idx < NA) out[NA * DK + idx] = 1.0f;
}

// ---------------------------------------------------------------------------
extern "C" void kernel_launch(void* const* d_in, const int* in_sizes, int n_in,
                              void* d_out, int out_size)
{
    const float* a_z    = (const float*)d_in[0];
    const float* bv_z   = (const float*)d_in[1];
    const int*   mask   = (const int*)d_in[2];   // jnp bool -> int32 per harness
    const float* weight = (const float*)d_in[3];
    const float* Wq     = (const float*)d_in[4];
    const float* Wk     = (const float*)d_in[5];
    const float* Wv     = (const float*)d_in[6];
    float* out = (float*)d_out;

    cudaFuncSetAttribute(attn_kernel,
                         cudaFuncAttributeMaxDynamicSharedMemorySize, SME_TOT);

    proj_kernel<<<dim3(NA / PTILE, D / PTILE, 3), 256>>>(a_z, bv_z, Wq, Wk, Wv);
    wb_kernel<<<(NA * (size_t)NB) / (256 * 4), 256>>>(mask, weight);
    attn_kernel<<<dim3(NA / QM, H), 256, SME_TOT>>>();
    combine_kernel<<<(NA * DK + 255) / 256, 256>>>(out);
}